// round 12
// baseline (speedup 1.0000x reference)
#include <cuda_runtime.h>
#include <math.h>

#define CC 256
#define HH 64
#define NPIX (HH*HH)
typedef unsigned long long u64;

// region offsets (elements) inside per-scale concatenated buffers
#define OFF2   (CC*NPIX)                 // dw/pos scale-2 start
#define OFF4   (CC*NPIX + CC*1024)       // dw/pos scale-4 start
#define TOTPIX (NPIX + 1024 + 256)       // 5376 pixels across scales
#define QOFF2  (3*CC*NPIX)
#define QOFF4  (3*CC*NPIX + 3*CC*1024)

// ---------------- packed f32x2 helpers ----------------
__device__ __forceinline__ void ffma2(u64 &d, u64 a, u64 b) {
    asm("fma.rn.f32x2 %0, %1, %2, %0;" : "+l"(d) : "l"(a), "l"(b));
}
__device__ __forceinline__ float2 unpack2(u64 v) {
    float2 r; asm("mov.b64 {%0, %1}, %2;" : "=f"(r.x), "=f"(r.y) : "l"(v)); return r;
}

// ---------------- scratch ----------------
__device__ float g_xs [CC*(1024+256)];   // pooled inputs: s2 then s4
__device__ float g_dw [CC*TOTPIX];
__device__ float g_pos[CC*TOTPIX];
__device__ float g_qkv[3*CC*TOTPIX];
__device__ float g_att[CC*(1024+256)];   // attn out s2, s4 (pre-upsample)
__device__ float g_cat[3*CC*NPIX];

// ---------------- avg pool, both scales in one launch ----------------
__global__ void pool_all_kernel(const float* __restrict__ x,
                                float* __restrict__ xs2, float* __restrict__ xs4) {
    int b = blockIdx.x;
    int s, Hs, idx; float* out;
    if (b < 1024) { s = 2; Hs = 32; out = xs2; idx = b * 256 + threadIdx.x; }
    else          { s = 4; Hs = 16; out = xs4; idx = (b - 1024) * 256 + threadIdx.x; }
    int xo = idx % Hs, yo = (idx / Hs) % Hs, c = idx / (Hs * Hs);
    const float* xp = x + c * NPIX + (yo * s) * HH + xo * s;
    float sum = 0.f;
    for (int dy = 0; dy < s; dy++)
        for (int dx = 0; dx < s; dx++) sum += xp[dy * HH + dx];
    out[idx] = sum * (1.0f / (s * s));
}

// ---------------- fused depthwise 3x3 (dw + pos), all scales ----------------
__global__ void dwconv_all_kernel(const float* __restrict__ x,
                                  const float* __restrict__ xs2, const float* __restrict__ xs4,
                                  const float* __restrict__ dw_w, const float* __restrict__ dw_b,
                                  const float* __restrict__ pos_w, const float* __restrict__ pos_b,
                                  float* __restrict__ dwout, float* __restrict__ posout) {
    int b = blockIdx.x;
    int i, Hs, off, bl; const float* src;
    if (b < 4096)      { i = 0; Hs = 64; src = x;   off = 0;    bl = b; }
    else if (b < 5120) { i = 1; Hs = 32; src = xs2; off = OFF2; bl = b - 4096; }
    else               { i = 2; Hs = 16; src = xs4; off = OFF4; bl = b - 5120; }
    int idx = bl * 256 + threadIdx.x;
    int x0 = idx % Hs, y0 = (idx / Hs) % Hs, c = idx / (Hs * Hs);
    const float* xp = src + c * Hs * Hs;
    const float* wd = dw_w + i * CC * 9 + c * 9;
    const float* wp = pos_w + i * CC * 9 + c * 9;
    float a = dw_b[i * CC + c], p = pos_b[i * CC + c];
#pragma unroll
    for (int ky = 0; ky < 3; ky++) {
        int y = y0 + ky - 1;
        if ((unsigned)y >= (unsigned)Hs) continue;
#pragma unroll
        for (int kx = 0; kx < 3; kx++) {
            int xx = x0 + kx - 1;
            if ((unsigned)xx >= (unsigned)Hs) continue;
            float v = __ldg(xp + y * Hs + xx);
            a = fmaf(v, wd[ky * 3 + kx], a);
            p = fmaf(v, wp[ky * 3 + kx], p);
        }
    }
    dwout[off + idx]  = a;
    posout[off + idx] = p;
}

// ---------------- shared GEMM tile body (FFMA2, dup-A in smem) ----------------
// C[64x64 tile] = W[M,K]*A[K,N] + bias, optional +pos for rows m<512
template <bool ADD_POS>
__device__ __forceinline__ void gemm_tile(const float* __restrict__ W, const float* __restrict__ A,
                                          const float* __restrict__ bias, const float* __restrict__ pos,
                                          float* __restrict__ Cout, int Kd, int N, int m0, int n0) {
    __shared__ __align__(16) float Wt [16][68];    // [k][m]
    __shared__ __align__(16) float As2[16][128];   // [k][n duplicated]
    int tid = threadIdx.x;
    int ty = tid >> 4, tx = tid & 15;
    int wm = tid >> 2, wk4 = (tid & 3) * 4;
    int ak = tid >> 4, an4 = (tid & 15) * 4;
    u64 c2[2][4] = {};                             // [m-pair][j]
    for (int k0 = 0; k0 < Kd; k0 += 16) {
        float4 wv = *(const float4*)(W + (size_t)(m0 + wm) * Kd + k0 + wk4);
        Wt[wk4 + 0][wm] = wv.x; Wt[wk4 + 1][wm] = wv.y;
        Wt[wk4 + 2][wm] = wv.z; Wt[wk4 + 3][wm] = wv.w;
        float4 av = *(const float4*)(A + (size_t)(k0 + ak) * N + n0 + an4);
        *(float4*)(&As2[ak][an4 * 2    ]) = make_float4(av.x, av.x, av.y, av.y);
        *(float4*)(&As2[ak][an4 * 2 + 4]) = make_float4(av.z, av.z, av.w, av.w);
        __syncthreads();
#pragma unroll
        for (int k = 0; k < 16; k++) {
            ulonglong2 ww = *(const ulonglong2*)(&Wt[k][ty * 4]);     // (w0,w1),(w2,w3)
            ulonglong2 a01 = *(const ulonglong2*)(&As2[k][tx * 8]);   // (a0,a0),(a1,a1)
            ulonglong2 a23 = *(const ulonglong2*)(&As2[k][tx * 8 + 4]);
            ffma2(c2[0][0], ww.x, a01.x); ffma2(c2[0][1], ww.x, a01.y);
            ffma2(c2[0][2], ww.x, a23.x); ffma2(c2[0][3], ww.x, a23.y);
            ffma2(c2[1][0], ww.y, a01.x); ffma2(c2[1][1], ww.y, a01.y);
            ffma2(c2[1][2], ww.y, a23.x); ffma2(c2[1][3], ww.y, a23.y);
        }
        __syncthreads();
    }
#pragma unroll
    for (int ipair = 0; ipair < 2; ipair++) {
#pragma unroll
        for (int j = 0; j < 4; j++) {
            float2 v = unpack2(c2[ipair][j]);
            int n = n0 + tx * 4 + j;
            float vv[2] = {v.x, v.y};
#pragma unroll
            for (int hh = 0; hh < 2; hh++) {
                int m = m0 + ty * 4 + ipair * 2 + hh;
                float val = vv[hh] + bias[m];
                if (ADD_POS) { if (m < 512) val += pos[(size_t)(m & 255) * N + n]; }
                Cout[(size_t)m * N + n] = val;
            }
        }
    }
}

// QKV GEMMs for all 3 scales in one launch (M=768, K=256 each)
__global__ __launch_bounds__(256)
void qkv_gemm_kernel(const float* __restrict__ pw_w, const float* __restrict__ dw,
                     const float* __restrict__ pw_b, const float* __restrict__ pos,
                     float* __restrict__ qkv) {
    int b = blockIdx.x;
    int i, N, bx, by, off, qoff;
    if (b < 768)      { i = 0; N = 4096; bx = b & 63;  by = b >> 6;         off = 0;    qoff = 0; }
    else if (b < 960) { i = 1; N = 1024; bx = (b-768) & 15; by = (b-768) >> 4; off = OFF2; qoff = QOFF2; }
    else              { i = 2; N = 256;  bx = (b-960) & 3;  by = (b-960) >> 2; off = OFF4; qoff = QOFF4; }
    gemm_tile<true>(pw_w + (size_t)i * 768 * 256, dw + off, pw_b + i * 768,
                    pos + off, qkv + qoff, 256, N, by * 64, bx * 64);
}

// fusion GEMM: out(256,4096) = fus_w(256,768) * cat(768,4096) + fus_b
__global__ __launch_bounds__(256)
void fusion_gemm_kernel(const float* __restrict__ fus_w, const float* __restrict__ cat,
                        const float* __restrict__ fus_b, float* __restrict__ out) {
    gemm_tile<false>(fus_w, cat, fus_b, nullptr, out, 3 * CC, NPIX,
                     blockIdx.y * 64, blockIdx.x * 64);
}

// ---------------- flash attention, no-max softmax, all scales ----------------
// dynamic smem layout: Qd[32][128] | Ks[2][32][64] | Vs[2][32][68] | S[64][64]
__global__ __launch_bounds__(256)
void attn_all_kernel(const float* __restrict__ qkv_base, float* __restrict__ cat,
                     float* __restrict__ att) {
    extern __shared__ float sm[];
    float (*Qd)[128]     = (float(*)[128])(sm);
    float (*Ks)[32][64]  = (float(*)[32][64])(sm + 4096);
    float (*Vs)[32][68]  = (float(*)[32][68])(sm + 8192);
    float (*S)[64]       = (float(*)[64])(sm + 12544);

    int b = blockIdx.x;
    const float* qkv; float* out; int N, h, n0;
    if (b < 512)      { qkv = qkv_base;          out = cat;            N = 4096; h = b >> 6;       n0 = (b & 63) * 64; }
    else if (b < 640) { qkv = qkv_base + QOFF2;  out = att;            N = 1024; h = (b-512) >> 4; n0 = ((b-512) & 15) * 64; }
    else              { qkv = qkv_base + QOFF4;  out = att + CC*1024;  N = 256;  h = (b-640) >> 2; n0 = ((b-640) & 3) * 64; }

    int tid = threadIdx.x;
    const float scale = 0.17677669529663687f;    // 1/sqrt(32)
    const float* qb = qkv + (size_t)(h * 32) * N + n0;
    const float* kb = qkv + (size_t)(256 + h * 32) * N;
    const float* vb = qkv + (size_t)(512 + h * 32) * N;

    int ty = tid >> 4, tx = tid & 15;
    int ld_d = tid >> 4;                 // 0..15 (two d's per thread via r)
    int ld_m = (tid & 15) * 4;

    // load Q tile, scaled + duplicated
#pragma unroll
    for (int r = 0; r < 2; r++) {
        int idx4 = tid + r * 256;
        int d = idx4 >> 4, nq = (idx4 & 15) * 4;
        float4 qv = *(const float4*)(qb + (size_t)d * N + nq);
        qv.x *= scale; qv.y *= scale; qv.z *= scale; qv.w *= scale;
        *(float4*)(&Qd[d][nq * 2    ]) = make_float4(qv.x, qv.x, qv.y, qv.y);
        *(float4*)(&Qd[d][nq * 2 + 4]) = make_float4(qv.z, qv.z, qv.w, qv.w);
    }

    float l_p[4] = {0.f, 0.f, 0.f, 0.f};
    u64 acc2[4][2] = {};                 // [row][d-half], packed pairs along m

    // preload tile 0
    float4 kr[2], vr[2];
#pragma unroll
    for (int r = 0; r < 2; r++) {
        int d = ld_d + r * 16;
        kr[r] = *(const float4*)(kb + (size_t)d * N + ld_m);
        vr[r] = *(const float4*)(vb + (size_t)d * N + ld_m);
    }
#pragma unroll
    for (int r = 0; r < 2; r++) {
        int d = ld_d + r * 16;
        *(float4*)(&Ks[0][d][ld_m]) = kr[r];
        *(float4*)(&Vs[0][d][ld_m]) = vr[r];
    }
    __syncthreads();

    int T = N >> 6;
    for (int t = 0; t < T; t++) {
        int cur = t & 1;
        if (t + 1 < T) {
            int m0 = (t + 1) * 64;
#pragma unroll
            for (int r = 0; r < 2; r++) {
                int d = ld_d + r * 16;
                kr[r] = *(const float4*)(kb + (size_t)d * N + m0 + ld_m);
                vr[r] = *(const float4*)(vb + (size_t)d * N + m0 + ld_m);
            }
        }

        // ---- S = Q^T K, pairs along key-column ----
        u64 c2[4][2] = {};               // [row][j-pair]
#pragma unroll
        for (int d = 0; d < 32; d++) {
            ulonglong2 qa  = *(const ulonglong2*)(&Qd[d][ty * 8]);      // (q0,q0),(q1,q1)
            ulonglong2 qb2 = *(const ulonglong2*)(&Qd[d][ty * 8 + 4]);  // (q2,q2),(q3,q3)
            ulonglong2 kk  = *(const ulonglong2*)(&Ks[cur][d][tx * 4]); // (k0,k1),(k2,k3)
            ffma2(c2[0][0], qa.x,  kk.x); ffma2(c2[0][1], qa.x,  kk.y);
            ffma2(c2[1][0], qa.y,  kk.x); ffma2(c2[1][1], qa.y,  kk.y);
            ffma2(c2[2][0], qb2.x, kk.x); ffma2(c2[2][1], qb2.x, kk.y);
            ffma2(c2[3][0], qb2.y, kk.x); ffma2(c2[3][1], qb2.y, kk.y);
        }

        // ---- softmax numerator: plain exp (scores are O(1); shift-invariant) ----
#pragma unroll
        for (int i = 0; i < 4; i++) {
            float2 v01 = unpack2(c2[i][0]);
            float2 v23 = unpack2(c2[i][1]);
            float e0 = __expf(v01.x), e1 = __expf(v01.y);
            float e2 = __expf(v23.x), e3 = __expf(v23.y);
            l_p[i] += (e0 + e1) + (e2 + e3);
            *(float4*)(&S[ty * 4 + i][tx * 4]) = make_float4(e0, e1, e2, e3);
        }
        __syncwarp();                    // S rows 8w..8w+7 are warp-private

        // ---- O += P V^T, packed pairs along m ----
#pragma unroll
        for (int m4 = 0; m4 < 16; m4++) {
            ulonglong2 va  = *(const ulonglong2*)(&Vs[cur][tx     ][m4 * 4]);
            ulonglong2 vbb = *(const ulonglong2*)(&Vs[cur][tx + 16][m4 * 4]);
#pragma unroll
            for (int i = 0; i < 4; i++) {
                ulonglong2 pp = *(const ulonglong2*)(&S[ty * 4 + i][m4 * 4]);
                ffma2(acc2[i][0], pp.x, va.x);  ffma2(acc2[i][0], pp.y, va.y);
                ffma2(acc2[i][1], pp.x, vbb.x); ffma2(acc2[i][1], pp.y, vbb.y);
            }
        }

        if (t + 1 < T) {
#pragma unroll
            for (int r = 0; r < 2; r++) {
                int d = ld_d + r * 16;
                *(float4*)(&Ks[cur ^ 1][d][ld_m]) = kr[r];
                *(float4*)(&Vs[cur ^ 1][d][ld_m]) = vr[r];
            }
        }
        __syncthreads();
    }

    // reduce l across the 16 column-lanes (once, after the whole loop)
#pragma unroll
    for (int off = 1; off < 16; off <<= 1) {
#pragma unroll
        for (int i = 0; i < 4; i++)
            l_p[i] += __shfl_xor_sync(0xffffffffu, l_p[i], off);
    }

    // finalize: horizontal add, normalize, stage transposed, coalesced store
#pragma unroll
    for (int i = 0; i < 4; i++) {
        float inv = 1.0f / l_p[i];
        float2 s0 = unpack2(acc2[i][0]);
        float2 s1 = unpack2(acc2[i][1]);
        S[tx     ][ty * 4 + i] = (s0.x + s0.y) * inv;
        S[tx + 16][ty * 4 + i] = (s1.x + s1.y) * inv;
    }
    __syncthreads();
#pragma unroll
    for (int r = 0; r < 2; r++) {
        int idx4 = tid + r * 256;              // 512 float4 slots over 32x64
        int d = idx4 >> 4, n4 = (idx4 & 15) * 4;
        *(float4*)(out + (size_t)(h * 32 + d) * N + n0 + n4) = *(const float4*)(&S[d][n4]);
    }
}

// ---------------- bilinear upsample (jax.image.resize), both scales ----------------
__global__ void upsample_all_kernel(const float* __restrict__ att, float* __restrict__ cat) {
    int b = blockIdx.x;
    const float* in; float* dst; int s, Hs, idx;
    if (b < 4096) { in = att;            dst = cat + (size_t)CC * NPIX;     s = 2; Hs = 32; idx = b * 256 + threadIdx.x; }
    else          { in = att + CC*1024;  dst = cat + (size_t)2 * CC * NPIX; s = 4; Hs = 16; idx = (b - 4096) * 256 + threadIdx.x; }
    int xo = idx & 63, yo = (idx >> 6) & 63, c = idx >> 12;
    float fs = 1.0f / s;
    float fy = (yo + 0.5f) * fs - 0.5f;
    float fx = (xo + 0.5f) * fs - 0.5f;
    float fy0 = floorf(fy), fx0 = floorf(fx);
    float wy = fy - fy0, wx = fx - fx0;
    int y0 = (int)fy0, x0 = (int)fx0;
    int y0c = max(y0, 0), y1c = min(y0 + 1, Hs - 1);
    int x0c = max(x0, 0), x1c = min(x0 + 1, Hs - 1);
    const float* ip = in + (size_t)c * Hs * Hs;
    float v00 = ip[y0c * Hs + x0c], v01 = ip[y0c * Hs + x1c];
    float v10 = ip[y1c * Hs + x0c], v11 = ip[y1c * Hs + x1c];
    float v0 = v00 + (v01 - v00) * wx;
    float v1 = v10 + (v11 - v10) * wx;
    dst[idx] = v0 + (v1 - v0) * wy;
}

// ---------------- host launch ----------------
extern "C" void kernel_launch(void* const* d_in, const int* in_sizes, int n_in,
                              void* d_out, int out_size) {
    const float* x     = (const float*)d_in[0];
    const float* dw_w  = (const float*)d_in[1];
    const float* dw_b  = (const float*)d_in[2];
    const float* pw_w  = (const float*)d_in[3];
    const float* pw_b  = (const float*)d_in[4];
    const float* pos_w = (const float*)d_in[5];
    const float* pos_b = (const float*)d_in[6];
    const float* fus_w = (const float*)d_in[7];
    const float* fus_b = (const float*)d_in[8];
    float* out = (float*)d_out;

    static int attr_done = 0;
    if (!attr_done) {
        cudaFuncSetAttribute(attn_all_kernel, cudaFuncAttributeMaxDynamicSharedMemorySize, 66560);
        attr_done = 1;
    }

    float *xs, *dw, *pos, *qkv, *att, *cat;
    cudaGetSymbolAddress((void**)&xs,  g_xs);
    cudaGetSymbolAddress((void**)&dw,  g_dw);
    cudaGetSymbolAddress((void**)&pos, g_pos);
    cudaGetSymbolAddress((void**)&qkv, g_qkv);
    cudaGetSymbolAddress((void**)&att, g_att);
    cudaGetSymbolAddress((void**)&cat, g_cat);

    float* xs2 = xs;
    float* xs4 = xs + CC * 1024;

    pool_all_kernel  <<<1280, 256>>>(x, xs2, xs4);
    dwconv_all_kernel<<<5376, 256>>>(x, xs2, xs4, dw_w, dw_b, pos_w, pos_b, dw, pos);
    qkv_gemm_kernel  <<<1008, 256>>>(pw_w, dw, pw_b, pos, qkv);
    attn_all_kernel  <<<672, 256, 66560>>>(qkv, cat, att);
    upsample_all_kernel<<<8192, 256>>>(att, cat);
    fusion_gemm_kernel<<<dim3(64, 4), 256>>>(fus_w, cat, fus_b, out);
}

// round 13
// speedup vs baseline: 1.0018x; 1.0018x over previous
#include <cuda_runtime.h>
#include <math.h>

#define CC 256
#define HH 64
#define NPIX (HH*HH)
typedef unsigned long long u64;

// region offsets (elements) inside per-scale concatenated buffers
#define OFF2   (CC*NPIX)                 // dw/pos scale-2 start
#define OFF4   (CC*NPIX + CC*1024)       // dw/pos scale-4 start
#define TOTPIX (NPIX + 1024 + 256)       // 5376 pixels across scales
#define QOFF2  (3*CC*NPIX)
#define QOFF4  (3*CC*NPIX + 3*CC*1024)

// ---------------- packed f32x2 helpers ----------------
__device__ __forceinline__ void ffma2(u64 &d, u64 a, u64 b) {
    asm("fma.rn.f32x2 %0, %1, %2, %0;" : "+l"(d) : "l"(a), "l"(b));
}
__device__ __forceinline__ float2 unpack2(u64 v) {
    float2 r; asm("mov.b64 {%0, %1}, %2;" : "=f"(r.x), "=f"(r.y) : "l"(v)); return r;
}

// ---------------- scratch ----------------
__device__ float g_xs [CC*(1024+256)];   // pooled inputs: s2 then s4
__device__ float g_dw [CC*TOTPIX];
__device__ float g_pos[CC*TOTPIX];
__device__ float g_qkv[3*CC*TOTPIX];
__device__ float g_att[CC*(1024+256)];   // attn out s2, s4 (pre-upsample)
__device__ float g_cat[3*CC*NPIX];

// ---------------- avg pool, both scales in one launch ----------------
__global__ void pool_all_kernel(const float* __restrict__ x,
                                float* __restrict__ xs2, float* __restrict__ xs4) {
    int b = blockIdx.x;
    int s, Hs, idx; float* out;
    if (b < 1024) { s = 2; Hs = 32; out = xs2; idx = b * 256 + threadIdx.x; }
    else          { s = 4; Hs = 16; out = xs4; idx = (b - 1024) * 256 + threadIdx.x; }
    int xo = idx % Hs, yo = (idx / Hs) % Hs, c = idx / (Hs * Hs);
    const float* xp = x + c * NPIX + (yo * s) * HH + xo * s;
    float sum = 0.f;
    for (int dy = 0; dy < s; dy++)
        for (int dx = 0; dx < s; dx++) sum += xp[dy * HH + dx];
    out[idx] = sum * (1.0f / (s * s));
}

// ---------------- fused depthwise 3x3 (dw + pos), all scales ----------------
__global__ void dwconv_all_kernel(const float* __restrict__ x,
                                  const float* __restrict__ xs2, const float* __restrict__ xs4,
                                  const float* __restrict__ dw_w, const float* __restrict__ dw_b,
                                  const float* __restrict__ pos_w, const float* __restrict__ pos_b,
                                  float* __restrict__ dwout, float* __restrict__ posout) {
    int b = blockIdx.x;
    int i, Hs, off, bl; const float* src;
    if (b < 4096)      { i = 0; Hs = 64; src = x;   off = 0;    bl = b; }
    else if (b < 5120) { i = 1; Hs = 32; src = xs2; off = OFF2; bl = b - 4096; }
    else               { i = 2; Hs = 16; src = xs4; off = OFF4; bl = b - 5120; }
    int idx = bl * 256 + threadIdx.x;
    int x0 = idx % Hs, y0 = (idx / Hs) % Hs, c = idx / (Hs * Hs);
    const float* xp = src + c * Hs * Hs;
    const float* wd = dw_w + i * CC * 9 + c * 9;
    const float* wp = pos_w + i * CC * 9 + c * 9;
    float a = dw_b[i * CC + c], p = pos_b[i * CC + c];
#pragma unroll
    for (int ky = 0; ky < 3; ky++) {
        int y = y0 + ky - 1;
        if ((unsigned)y >= (unsigned)Hs) continue;
#pragma unroll
        for (int kx = 0; kx < 3; kx++) {
            int xx = x0 + kx - 1;
            if ((unsigned)xx >= (unsigned)Hs) continue;
            float v = __ldg(xp + y * Hs + xx);
            a = fmaf(v, wd[ky * 3 + kx], a);
            p = fmaf(v, wp[ky * 3 + kx], p);
        }
    }
    dwout[off + idx]  = a;
    posout[off + idx] = p;
}

// ---------------- shared GEMM tile body (FFMA2, dup-A in smem) ----------------
// C[64x64 tile] = W[M,K]*A[K,N] + bias, optional +pos for rows m<512
template <bool ADD_POS>
__device__ __forceinline__ void gemm_tile(const float* __restrict__ W, const float* __restrict__ A,
                                          const float* __restrict__ bias, const float* __restrict__ pos,
                                          float* __restrict__ Cout, int Kd, int N, int m0, int n0) {
    __shared__ __align__(16) float Wt [16][68];    // [k][m]
    __shared__ __align__(16) float As2[16][128];   // [k][n duplicated]
    int tid = threadIdx.x;
    int ty = tid >> 4, tx = tid & 15;
    int wm = tid >> 2, wk4 = (tid & 3) * 4;
    int ak = tid >> 4, an4 = (tid & 15) * 4;
    u64 c2[2][4] = {};                             // [m-pair][j]
    for (int k0 = 0; k0 < Kd; k0 += 16) {
        float4 wv = *(const float4*)(W + (size_t)(m0 + wm) * Kd + k0 + wk4);
        Wt[wk4 + 0][wm] = wv.x; Wt[wk4 + 1][wm] = wv.y;
        Wt[wk4 + 2][wm] = wv.z; Wt[wk4 + 3][wm] = wv.w;
        float4 av = *(const float4*)(A + (size_t)(k0 + ak) * N + n0 + an4);
        *(float4*)(&As2[ak][an4 * 2    ]) = make_float4(av.x, av.x, av.y, av.y);
        *(float4*)(&As2[ak][an4 * 2 + 4]) = make_float4(av.z, av.z, av.w, av.w);
        __syncthreads();
#pragma unroll
        for (int k = 0; k < 16; k++) {
            ulonglong2 ww = *(const ulonglong2*)(&Wt[k][ty * 4]);     // (w0,w1),(w2,w3)
            ulonglong2 a01 = *(const ulonglong2*)(&As2[k][tx * 8]);   // (a0,a0),(a1,a1)
            ulonglong2 a23 = *(const ulonglong2*)(&As2[k][tx * 8 + 4]);
            ffma2(c2[0][0], ww.x, a01.x); ffma2(c2[0][1], ww.x, a01.y);
            ffma2(c2[0][2], ww.x, a23.x); ffma2(c2[0][3], ww.x, a23.y);
            ffma2(c2[1][0], ww.y, a01.x); ffma2(c2[1][1], ww.y, a01.y);
            ffma2(c2[1][2], ww.y, a23.x); ffma2(c2[1][3], ww.y, a23.y);
        }
        __syncthreads();
    }
#pragma unroll
    for (int ipair = 0; ipair < 2; ipair++) {
#pragma unroll
        for (int j = 0; j < 4; j++) {
            float2 v = unpack2(c2[ipair][j]);
            int n = n0 + tx * 4 + j;
            float vv[2] = {v.x, v.y};
#pragma unroll
            for (int hh = 0; hh < 2; hh++) {
                int m = m0 + ty * 4 + ipair * 2 + hh;
                float val = vv[hh] + bias[m];
                if (ADD_POS) { if (m < 512) val += pos[(size_t)(m & 255) * N + n]; }
                Cout[(size_t)m * N + n] = val;
            }
        }
    }
}

// QKV GEMMs for all 3 scales in one launch (M=768, K=256 each)
__global__ __launch_bounds__(256)
void qkv_gemm_kernel(const float* __restrict__ pw_w, const float* __restrict__ dw,
                     const float* __restrict__ pw_b, const float* __restrict__ pos,
                     float* __restrict__ qkv) {
    int b = blockIdx.x;
    int i, N, bx, by, off, qoff;
    if (b < 768)      { i = 0; N = 4096; bx = b & 63;  by = b >> 6;         off = 0;    qoff = 0; }
    else if (b < 960) { i = 1; N = 1024; bx = (b-768) & 15; by = (b-768) >> 4; off = OFF2; qoff = QOFF2; }
    else              { i = 2; N = 256;  bx = (b-960) & 3;  by = (b-960) >> 2; off = OFF4; qoff = QOFF4; }
    gemm_tile<true>(pw_w + (size_t)i * 768 * 256, dw + off, pw_b + i * 768,
                    pos + off, qkv + qoff, 256, N, by * 64, bx * 64);
}

// fusion GEMM: out(256,4096) = fus_w(256,768) * cat(768,4096) + fus_b
__global__ __launch_bounds__(256)
void fusion_gemm_kernel(const float* __restrict__ fus_w, const float* __restrict__ cat,
                        const float* __restrict__ fus_b, float* __restrict__ out) {
    gemm_tile<false>(fus_w, cat, fus_b, nullptr, out, 3 * CC, NPIX,
                     blockIdx.y * 64, blockIdx.x * 64);
}

// ---------------- flash attention, no-max softmax, all scales ----------------
// dynamic smem layout: Qd[32][128] | Ks[2][32][64] | Vs[2][32][68] | S[64][64]
__global__ __launch_bounds__(256)
void attn_all_kernel(const float* __restrict__ qkv_base, float* __restrict__ cat,
                     float* __restrict__ att) {
    extern __shared__ float sm[];
    float (*Qd)[128]     = (float(*)[128])(sm);
    float (*Ks)[32][64]  = (float(*)[32][64])(sm + 4096);
    float (*Vs)[32][68]  = (float(*)[32][68])(sm + 8192);
    float (*S)[64]       = (float(*)[64])(sm + 12544);

    int b = blockIdx.x;
    const float* qkv; float* out; int N, h, n0;
    if (b < 512)      { qkv = qkv_base;          out = cat;            N = 4096; h = b >> 6;       n0 = (b & 63) * 64; }
    else if (b < 640) { qkv = qkv_base + QOFF2;  out = att;            N = 1024; h = (b-512) >> 4; n0 = ((b-512) & 15) * 64; }
    else              { qkv = qkv_base + QOFF4;  out = att + CC*1024;  N = 256;  h = (b-640) >> 2; n0 = ((b-640) & 3) * 64; }

    int tid = threadIdx.x;
    const float scale = 0.17677669529663687f;    // 1/sqrt(32)
    const float* qb = qkv + (size_t)(h * 32) * N + n0;
    const float* kb = qkv + (size_t)(256 + h * 32) * N;
    const float* vb = qkv + (size_t)(512 + h * 32) * N;

    int ty = tid >> 4, tx = tid & 15;
    int ld_d = tid >> 4;                 // 0..15 (two d's per thread via r)
    int ld_m = (tid & 15) * 4;

    // load Q tile, scaled + duplicated
#pragma unroll
    for (int r = 0; r < 2; r++) {
        int idx4 = tid + r * 256;
        int d = idx4 >> 4, nq = (idx4 & 15) * 4;
        float4 qv = *(const float4*)(qb + (size_t)d * N + nq);
        qv.x *= scale; qv.y *= scale; qv.z *= scale; qv.w *= scale;
        *(float4*)(&Qd[d][nq * 2    ]) = make_float4(qv.x, qv.x, qv.y, qv.y);
        *(float4*)(&Qd[d][nq * 2 + 4]) = make_float4(qv.z, qv.z, qv.w, qv.w);
    }

    float l_p[4] = {0.f, 0.f, 0.f, 0.f};
    u64 acc2[4][2] = {};                 // [row][d-half], packed pairs along m

    // preload tile 0
    float4 kr[2], vr[2];
#pragma unroll
    for (int r = 0; r < 2; r++) {
        int d = ld_d + r * 16;
        kr[r] = *(const float4*)(kb + (size_t)d * N + ld_m);
        vr[r] = *(const float4*)(vb + (size_t)d * N + ld_m);
    }
#pragma unroll
    for (int r = 0; r < 2; r++) {
        int d = ld_d + r * 16;
        *(float4*)(&Ks[0][d][ld_m]) = kr[r];
        *(float4*)(&Vs[0][d][ld_m]) = vr[r];
    }
    __syncthreads();

    int T = N >> 6;
    for (int t = 0; t < T; t++) {
        int cur = t & 1;
        if (t + 1 < T) {
            int m0 = (t + 1) * 64;
#pragma unroll
            for (int r = 0; r < 2; r++) {
                int d = ld_d + r * 16;
                kr[r] = *(const float4*)(kb + (size_t)d * N + m0 + ld_m);
                vr[r] = *(const float4*)(vb + (size_t)d * N + m0 + ld_m);
            }
        }

        // ---- S = Q^T K, pairs along key-column ----
        u64 c2[4][2] = {};               // [row][j-pair]
#pragma unroll
        for (int d = 0; d < 32; d++) {
            ulonglong2 qa  = *(const ulonglong2*)(&Qd[d][ty * 8]);      // (q0,q0),(q1,q1)
            ulonglong2 qb2 = *(const ulonglong2*)(&Qd[d][ty * 8 + 4]);  // (q2,q2),(q3,q3)
            ulonglong2 kk  = *(const ulonglong2*)(&Ks[cur][d][tx * 4]); // (k0,k1),(k2,k3)
            ffma2(c2[0][0], qa.x,  kk.x); ffma2(c2[0][1], qa.x,  kk.y);
            ffma2(c2[1][0], qa.y,  kk.x); ffma2(c2[1][1], qa.y,  kk.y);
            ffma2(c2[2][0], qb2.x, kk.x); ffma2(c2[2][1], qb2.x, kk.y);
            ffma2(c2[3][0], qb2.y, kk.x); ffma2(c2[3][1], qb2.y, kk.y);
        }

        // ---- softmax numerator: plain exp (scores are O(1); shift-invariant) ----
#pragma unroll
        for (int i = 0; i < 4; i++) {
            float2 v01 = unpack2(c2[i][0]);
            float2 v23 = unpack2(c2[i][1]);
            float e0 = __expf(v01.x), e1 = __expf(v01.y);
            float e2 = __expf(v23.x), e3 = __expf(v23.y);
            l_p[i] += (e0 + e1) + (e2 + e3);
            *(float4*)(&S[ty * 4 + i][tx * 4]) = make_float4(e0, e1, e2, e3);
        }
        __syncwarp();                    // S rows 8w..8w+7 are warp-private

        // ---- O += P V^T, packed pairs along m ----
#pragma unroll
        for (int m4 = 0; m4 < 16; m4++) {
            ulonglong2 va  = *(const ulonglong2*)(&Vs[cur][tx     ][m4 * 4]);
            ulonglong2 vbb = *(const ulonglong2*)(&Vs[cur][tx + 16][m4 * 4]);
#pragma unroll
            for (int i = 0; i < 4; i++) {
                ulonglong2 pp = *(const ulonglong2*)(&S[ty * 4 + i][m4 * 4]);
                ffma2(acc2[i][0], pp.x, va.x);  ffma2(acc2[i][0], pp.y, va.y);
                ffma2(acc2[i][1], pp.x, vbb.x); ffma2(acc2[i][1], pp.y, vbb.y);
            }
        }

        if (t + 1 < T) {
#pragma unroll
            for (int r = 0; r < 2; r++) {
                int d = ld_d + r * 16;
                *(float4*)(&Ks[cur ^ 1][d][ld_m]) = kr[r];
                *(float4*)(&Vs[cur ^ 1][d][ld_m]) = vr[r];
            }
        }
        __syncthreads();
    }

    // reduce l across the 16 column-lanes (once, after the whole loop)
#pragma unroll
    for (int off = 1; off < 16; off <<= 1) {
#pragma unroll
        for (int i = 0; i < 4; i++)
            l_p[i] += __shfl_xor_sync(0xffffffffu, l_p[i], off);
    }

    // finalize: horizontal add, normalize, stage transposed, coalesced store
#pragma unroll
    for (int i = 0; i < 4; i++) {
        float inv = 1.0f / l_p[i];
        float2 s0 = unpack2(acc2[i][0]);
        float2 s1 = unpack2(acc2[i][1]);
        S[tx     ][ty * 4 + i] = (s0.x + s0.y) * inv;
        S[tx + 16][ty * 4 + i] = (s1.x + s1.y) * inv;
    }
    __syncthreads();
#pragma unroll
    for (int r = 0; r < 2; r++) {
        int idx4 = tid + r * 256;              // 512 float4 slots over 32x64
        int d = idx4 >> 4, n4 = (idx4 & 15) * 4;
        *(float4*)(out + (size_t)(h * 32 + d) * N + n0 + n4) = *(const float4*)(&S[d][n4]);
    }
}

// ---------------- bilinear upsample (jax.image.resize), both scales ----------------
__global__ void upsample_all_kernel(const float* __restrict__ att, float* __restrict__ cat) {
    int b = blockIdx.x;
    const float* in; float* dst; int s, Hs, idx;
    if (b < 4096) { in = att;            dst = cat + (size_t)CC * NPIX;     s = 2; Hs = 32; idx = b * 256 + threadIdx.x; }
    else          { in = att + CC*1024;  dst = cat + (size_t)2 * CC * NPIX; s = 4; Hs = 16; idx = (b - 4096) * 256 + threadIdx.x; }
    int xo = idx & 63, yo = (idx >> 6) & 63, c = idx >> 12;
    float fs = 1.0f / s;
    float fy = (yo + 0.5f) * fs - 0.5f;
    float fx = (xo + 0.5f) * fs - 0.5f;
    float fy0 = floorf(fy), fx0 = floorf(fx);
    float wy = fy - fy0, wx = fx - fx0;
    int y0 = (int)fy0, x0 = (int)fx0;
    int y0c = max(y0, 0), y1c = min(y0 + 1, Hs - 1);
    int x0c = max(x0, 0), x1c = min(x0 + 1, Hs - 1);
    const float* ip = in + (size_t)c * Hs * Hs;
    float v00 = ip[y0c * Hs + x0c], v01 = ip[y0c * Hs + x1c];
    float v10 = ip[y1c * Hs + x0c], v11 = ip[y1c * Hs + x1c];
    float v0 = v00 + (v01 - v00) * wx;
    float v1 = v10 + (v11 - v10) * wx;
    dst[idx] = v0 + (v1 - v0) * wy;
}

// ---------------- host launch ----------------
extern "C" void kernel_launch(void* const* d_in, const int* in_sizes, int n_in,
                              void* d_out, int out_size) {
    const float* x     = (const float*)d_in[0];
    const float* dw_w  = (const float*)d_in[1];
    const float* dw_b  = (const float*)d_in[2];
    const float* pw_w  = (const float*)d_in[3];
    const float* pw_b  = (const float*)d_in[4];
    const float* pos_w = (const float*)d_in[5];
    const float* pos_b = (const float*)d_in[6];
    const float* fus_w = (const float*)d_in[7];
    const float* fus_b = (const float*)d_in[8];
    float* out = (float*)d_out;

    static int attr_done = 0;
    if (!attr_done) {
        cudaFuncSetAttribute(attn_all_kernel, cudaFuncAttributeMaxDynamicSharedMemorySize, 66560);
        attr_done = 1;
    }

    float *xs, *dw, *pos, *qkv, *att, *cat;
    cudaGetSymbolAddress((void**)&xs,  g_xs);
    cudaGetSymbolAddress((void**)&dw,  g_dw);
    cudaGetSymbolAddress((void**)&pos, g_pos);
    cudaGetSymbolAddress((void**)&qkv, g_qkv);
    cudaGetSymbolAddress((void**)&att, g_att);
    cudaGetSymbolAddress((void**)&cat, g_cat);

    float* xs2 = xs;
    float* xs4 = xs + CC * 1024;

    pool_all_kernel  <<<1280, 256>>>(x, xs2, xs4);
    dwconv_all_kernel<<<5376, 256>>>(x, xs2, xs4, dw_w, dw_b, pos_w, pos_b, dw, pos);
    qkv_gemm_kernel  <<<1008, 256>>>(pw_w, dw, pw_b, pos, qkv);
    attn_all_kernel  <<<672, 256, 66560>>>(qkv, cat, att);
    upsample_all_kernel<<<8192, 256>>>(att, cat);
    fusion_gemm_kernel<<<dim3(64, 4), 256>>>(fus_w, cat, fus_b, out);
}

// round 14
// speedup vs baseline: 1.2302x; 1.2280x over previous
#include <cuda_runtime.h>
#include <math.h>

#define CC 256
#define HH 64
#define NPIX (HH*HH)
typedef unsigned long long u64;

#define OFF2   (CC*NPIX)
#define OFF4   (CC*NPIX + CC*1024)
#define TOTPIX (NPIX + 1024 + 256)
#define QOFF2  (3*CC*NPIX)
#define QOFF4  (3*CC*NPIX + 3*CC*1024)

// ---------------- packed f32x2 helpers ----------------
__device__ __forceinline__ void ffma2(u64 &d, u64 a, u64 b) {
    asm("fma.rn.f32x2 %0, %1, %2, %0;" : "+l"(d) : "l"(a), "l"(b));
}
__device__ __forceinline__ u64 pack2(float lo, float hi) {
    u64 r; asm("mov.b64 %0, {%1, %2};" : "=l"(r) : "f"(lo), "f"(hi)); return r;
}
__device__ __forceinline__ float2 unpack2(u64 v) {
    float2 r; asm("mov.b64 {%0, %1}, %2;" : "=f"(r.x), "=f"(r.y) : "l"(v)); return r;
}

// ---------------- scratch ----------------
__device__ float g_xs [CC*(1024+256)];
__device__ float g_dw [CC*TOTPIX];
__device__ float g_pos[CC*TOTPIX];
__device__ float g_qkv[3*CC*TOTPIX];
__device__ float g_att[CC*(1024+256)];
__device__ float g_cat[3*CC*NPIX];

// ---------------- avg pool, both scales ----------------
__global__ void pool_all_kernel(const float* __restrict__ x,
                                float* __restrict__ xs2, float* __restrict__ xs4) {
    int b = blockIdx.x;
    int s, Hs, idx; float* out;
    if (b < 1024) { s = 2; Hs = 32; out = xs2; idx = b * 256 + threadIdx.x; }
    else          { s = 4; Hs = 16; out = xs4; idx = (b - 1024) * 256 + threadIdx.x; }
    int xo = idx % Hs, yo = (idx / Hs) % Hs, c = idx / (Hs * Hs);
    const float* xp = x + c * NPIX + (yo * s) * HH + xo * s;
    float sum = 0.f;
    for (int dy = 0; dy < s; dy++)
        for (int dx = 0; dx < s; dx++) sum += xp[dy * HH + dx];
    out[idx] = sum * (1.0f / (s * s));
}

// ---------------- fused depthwise 3x3 (dw + pos), all scales ----------------
__global__ void dwconv_all_kernel(const float* __restrict__ x,
                                  const float* __restrict__ xs2, const float* __restrict__ xs4,
                                  const float* __restrict__ dw_w, const float* __restrict__ dw_b,
                                  const float* __restrict__ pos_w, const float* __restrict__ pos_b,
                                  float* __restrict__ dwout, float* __restrict__ posout) {
    int b = blockIdx.x;
    int i, Hs, off, bl; const float* src;
    if (b < 4096)      { i = 0; Hs = 64; src = x;   off = 0;    bl = b; }
    else if (b < 5120) { i = 1; Hs = 32; src = xs2; off = OFF2; bl = b - 4096; }
    else               { i = 2; Hs = 16; src = xs4; off = OFF4; bl = b - 5120; }
    int idx = bl * 256 + threadIdx.x;
    int x0 = idx % Hs, y0 = (idx / Hs) % Hs, c = idx / (Hs * Hs);
    const float* xp = src + c * Hs * Hs;
    const float* wd = dw_w + i * CC * 9 + c * 9;
    const float* wp = pos_w + i * CC * 9 + c * 9;
    float a = dw_b[i * CC + c], p = pos_b[i * CC + c];
#pragma unroll
    for (int ky = 0; ky < 3; ky++) {
        int y = y0 + ky - 1;
        if ((unsigned)y >= (unsigned)Hs) continue;
#pragma unroll
        for (int kx = 0; kx < 3; kx++) {
            int xx = x0 + kx - 1;
            if ((unsigned)xx >= (unsigned)Hs) continue;
            float v = __ldg(xp + y * Hs + xx);
            a = fmaf(v, wd[ky * 3 + kx], a);
            p = fmaf(v, wp[ky * 3 + kx], p);
        }
    }
    dwout[off + idx]  = a;
    posout[off + idx] = p;
}

// ---------------- 128x128 GEMM tile, 8x8 micro, FFMA2 (pairs along m) ----------------
template <bool ADD_POS>
__device__ __forceinline__ void gemm_tile128(const float* __restrict__ W, const float* __restrict__ A,
                                             const float* __restrict__ bias, const float* __restrict__ pos,
                                             float* __restrict__ Cout, int Kd, int N, int m0, int n0) {
    __shared__ __align__(16) float Wt[16][132];   // [k][m]
    __shared__ __align__(16) float As[16][132];   // [k][n]
    int tid = threadIdx.x;
    int tm = tid >> 4, tn = tid & 15;
    int wm = tid >> 2, wk = (tid & 3) * 4;
    u64 acc[4][8] = {};                           // [m-pair][n]
    for (int k0 = 0; k0 < Kd; k0 += 16) {
#pragma unroll
        for (int r = 0; r < 2; r++) {
            int m = wm + r * 64;
            float4 wv = *(const float4*)(W + (size_t)(m0 + m) * Kd + k0 + wk);
            Wt[wk + 0][m] = wv.x; Wt[wk + 1][m] = wv.y;
            Wt[wk + 2][m] = wv.z; Wt[wk + 3][m] = wv.w;
        }
#pragma unroll
        for (int r = 0; r < 2; r++) {
            int idx = tid + r * 256;
            int k = idx >> 5, n4 = (idx & 31) * 4;
            *(float4*)(&As[k][n4]) = *(const float4*)(A + (size_t)(k0 + k) * N + n0 + n4);
        }
        __syncthreads();
#pragma unroll
        for (int k = 0; k < 16; k++) {
            ulonglong2 w01 = *(const ulonglong2*)(&Wt[k][tm * 8]);
            ulonglong2 w23 = *(const ulonglong2*)(&Wt[k][tm * 8 + 4]);
            float4 a0 = *(const float4*)(&As[k][tn * 8]);
            float4 a1 = *(const float4*)(&As[k][tn * 8 + 4]);
            u64 wp[4] = {w01.x, w01.y, w23.x, w23.y};
            u64 ad[8] = {pack2(a0.x, a0.x), pack2(a0.y, a0.y), pack2(a0.z, a0.z), pack2(a0.w, a0.w),
                         pack2(a1.x, a1.x), pack2(a1.y, a1.y), pack2(a1.z, a1.z), pack2(a1.w, a1.w)};
#pragma unroll
            for (int mp = 0; mp < 4; mp++)
#pragma unroll
                for (int j = 0; j < 8; j++)
                    ffma2(acc[mp][j], wp[mp], ad[j]);
        }
        __syncthreads();
    }
#pragma unroll
    for (int mp = 0; mp < 4; mp++) {
#pragma unroll
        for (int hh = 0; hh < 2; hh++) {
            int m = m0 + tm * 8 + mp * 2 + hh;
            float bv = bias[m];
            float v[8];
#pragma unroll
            for (int j = 0; j < 8; j++) {
                float2 p = unpack2(acc[mp][j]);
                v[j] = (hh ? p.y : p.x) + bv;
            }
            int n = n0 + tn * 8;
            if (ADD_POS) {
                if (m < 512) {
                    const float* pp = pos + (size_t)(m & 255) * N + n;
                    float4 p0 = *(const float4*)pp, p1 = *(const float4*)(pp + 4);
                    v[0] += p0.x; v[1] += p0.y; v[2] += p0.z; v[3] += p0.w;
                    v[4] += p1.x; v[5] += p1.y; v[6] += p1.z; v[7] += p1.w;
                }
            }
            float* cp = Cout + (size_t)m * N + n;
            *(float4*)cp       = make_float4(v[0], v[1], v[2], v[3]);
            *(float4*)(cp + 4) = make_float4(v[4], v[5], v[6], v[7]);
        }
    }
}

// QKV GEMMs for all 3 scales (M=768, K=256 each)
__global__ __launch_bounds__(256, 2)
void qkv_gemm_kernel(const float* __restrict__ pw_w, const float* __restrict__ dw,
                     const float* __restrict__ pw_b, const float* __restrict__ pos,
                     float* __restrict__ qkv) {
    int b = blockIdx.x;
    int i, N, bx, by, off, qoff;
    if (b < 192)      { i = 0; N = 4096; bx = b & 31;        by = b >> 5;        off = 0;    qoff = 0; }
    else if (b < 240) { i = 1; N = 1024; bx = (b - 192) & 7; by = (b - 192) >> 3; off = OFF2; qoff = QOFF2; }
    else              { i = 2; N = 256;  bx = (b - 240) & 1; by = (b - 240) >> 1; off = OFF4; qoff = QOFF4; }
    gemm_tile128<true>(pw_w + (size_t)i * 768 * 256, dw + off, pw_b + i * 768,
                       pos + off, qkv + qoff, 256, N, by * 128, bx * 128);
}

// fusion GEMM: out(256,4096) = fus_w(256,768) * cat(768,4096) + fus_b
__global__ __launch_bounds__(256, 2)
void fusion_gemm_kernel(const float* __restrict__ fus_w, const float* __restrict__ cat,
                        const float* __restrict__ fus_b, float* __restrict__ out) {
    int b = blockIdx.x;
    gemm_tile128<false>(fus_w, cat, fus_b, nullptr, out, 3 * CC, NPIX,
                        (b >> 5) * 128, (b & 31) * 128);
}

// ---------------- flash attention: Q-tile 128, K-tile 64, fat micro-tiles ----------------
// smem: Qs[32][132] | Ks[2][32][68] | Vs[2][32][68] | S[128][68]  = 86528 B
__global__ __launch_bounds__(256, 2)
void attn_all_kernel(const float* __restrict__ qkv_base, float* __restrict__ cat,
                     float* __restrict__ att) {
    extern __shared__ float sm[];
    float (*Qs)[132]    = (float(*)[132])(sm);
    float (*Ks)[32][68] = (float(*)[32][68])(sm + 32 * 132);
    float (*Vs)[32][68] = (float(*)[32][68])(sm + 32 * 132 + 2 * 32 * 68);
    float (*S)[68]      = (float(*)[68])(sm + 32 * 132 + 4 * 32 * 68);

    int b = blockIdx.x;
    const float* qkv; float* out; int N, h, n0;
    if (b < 256)      { qkv = qkv_base;         out = cat;             N = 4096; h = b >> 5;        n0 = (b & 31) * 128; }
    else if (b < 320) { qkv = qkv_base + QOFF2; out = att;             N = 1024; h = (b - 256) >> 3; n0 = ((b - 256) & 7) * 128; }
    else              { qkv = qkv_base + QOFF4; out = att + CC * 1024; N = 256;  h = (b - 320) >> 1; n0 = ((b - 320) & 1) * 128; }

    int tid = threadIdx.x;
    const float scale = 0.17677669529663687f;    // 1/sqrt(32)
    const float* qb = qkv + (size_t)(h * 32) * N + n0;
    const float* kb = qkv + (size_t)(256 + h * 32) * N;
    const float* vb = qkv + (size_t)(512 + h * 32) * N;

    int rg = tid >> 3;      // 0..31: rows rg*4..+3 (warp-private: warp w owns rows 16w..16w+15)
    int cg = tid & 7;       // QK: key cols cg*8..+7 ; PV: d = cg + dd*8

    // load Q tile 128x32, scaled
#pragma unroll
    for (int r = 0; r < 4; r++) {
        int idx = tid + r * 256;
        int d = idx >> 5, q4 = (idx & 31) * 4;
        float4 qv = *(const float4*)(qb + (size_t)d * N + q4);
        qv.x *= scale; qv.y *= scale; qv.z *= scale; qv.w *= scale;
        *(float4*)(&Qs[d][q4]) = qv;
    }

    float l_p[4] = {0.f, 0.f, 0.f, 0.f};
    u64 acc[4][4] = {};                 // [row i][dd], packed pairs along m

    int ld_d = tid >> 4, ld_m = (tid & 15) * 4;
    float4 kr[2], vr[2];
#pragma unroll
    for (int r = 0; r < 2; r++) {
        int d = ld_d + r * 16;
        kr[r] = *(const float4*)(kb + (size_t)d * N + ld_m);
        vr[r] = *(const float4*)(vb + (size_t)d * N + ld_m);
    }
#pragma unroll
    for (int r = 0; r < 2; r++) {
        int d = ld_d + r * 16;
        *(float4*)(&Ks[0][d][ld_m]) = kr[r];
        *(float4*)(&Vs[0][d][ld_m]) = vr[r];
    }
    __syncthreads();

    int T = N >> 6;
    for (int t = 0; t < T; t++) {
        int cur = t & 1;
        if (t + 1 < T) {
            int m0 = (t + 1) * 64;
#pragma unroll
            for (int r = 0; r < 2; r++) {
                int d = ld_d + r * 16;
                kr[r] = *(const float4*)(kb + (size_t)d * N + m0 + ld_m);
                vr[r] = *(const float4*)(vb + (size_t)d * N + m0 + ld_m);
            }
        }

        // ---- S = Q^T K : 4 rows x 8 keys, pairs along keys, Q dup via ALU ----
        u64 c2[4][4] = {};
#pragma unroll
        for (int d = 0; d < 32; d++) {
            float4 qf = *(const float4*)(&Qs[d][rg * 4]);
            ulonglong2 kk0 = *(const ulonglong2*)(&Ks[cur][d][cg * 8]);
            ulonglong2 kk1 = *(const ulonglong2*)(&Ks[cur][d][cg * 8 + 4]);
            u64 q0 = pack2(qf.x, qf.x), q1 = pack2(qf.y, qf.y);
            u64 q2 = pack2(qf.z, qf.z), q3 = pack2(qf.w, qf.w);
            ffma2(c2[0][0], q0, kk0.x); ffma2(c2[0][1], q0, kk0.y);
            ffma2(c2[0][2], q0, kk1.x); ffma2(c2[0][3], q0, kk1.y);
            ffma2(c2[1][0], q1, kk0.x); ffma2(c2[1][1], q1, kk0.y);
            ffma2(c2[1][2], q1, kk1.x); ffma2(c2[1][3], q1, kk1.y);
            ffma2(c2[2][0], q2, kk0.x); ffma2(c2[2][1], q2, kk0.y);
            ffma2(c2[2][2], q2, kk1.x); ffma2(c2[2][3], q2, kk1.y);
            ffma2(c2[3][0], q3, kk0.x); ffma2(c2[3][1], q3, kk0.y);
            ffma2(c2[3][2], q3, kk1.x); ffma2(c2[3][3], q3, kk1.y);
        }

        // ---- exp (no max-sub: scores O(1), shift-invariant), store S, track l ----
#pragma unroll
        for (int i = 0; i < 4; i++) {
            float2 p0 = unpack2(c2[i][0]), p1 = unpack2(c2[i][1]);
            float2 p2 = unpack2(c2[i][2]), p3 = unpack2(c2[i][3]);
            float e0 = __expf(p0.x), e1 = __expf(p0.y), e2 = __expf(p1.x), e3 = __expf(p1.y);
            float e4 = __expf(p2.x), e5 = __expf(p2.y), e6 = __expf(p3.x), e7 = __expf(p3.y);
            l_p[i] += ((e0 + e1) + (e2 + e3)) + ((e4 + e5) + (e6 + e7));
            *(float4*)(&S[rg * 4 + i][cg * 8])     = make_float4(e0, e1, e2, e3);
            *(float4*)(&S[rg * 4 + i][cg * 8 + 4]) = make_float4(e4, e5, e6, e7);
        }
        __syncwarp();     // S rows are warp-private

        // ---- O += P V^T : 4 rows x 4 dims (d = cg + dd*8), pairs along m ----
#pragma unroll
        for (int m4 = 0; m4 < 16; m4++) {
            ulonglong2 vv[4];
#pragma unroll
            for (int dd = 0; dd < 4; dd++)
                vv[dd] = *(const ulonglong2*)(&Vs[cur][cg + dd * 8][m4 * 4]);
#pragma unroll
            for (int i = 0; i < 4; i++) {
                ulonglong2 pp = *(const ulonglong2*)(&S[rg * 4 + i][m4 * 4]);
#pragma unroll
                for (int dd = 0; dd < 4; dd++) {
                    ffma2(acc[i][dd], pp.x, vv[dd].x);
                    ffma2(acc[i][dd], pp.y, vv[dd].y);
                }
            }
        }

        if (t + 1 < T) {
#pragma unroll
            for (int r = 0; r < 2; r++) {
                int d = ld_d + r * 16;
                *(float4*)(&Ks[cur ^ 1][d][ld_m]) = kr[r];
                *(float4*)(&Vs[cur ^ 1][d][ld_m]) = vr[r];
            }
        }
        __syncthreads();
    }

    // reduce l across the 8 cg lanes (same rg group lives in one warp)
#pragma unroll
    for (int off = 1; off < 8; off <<= 1)
#pragma unroll
        for (int i = 0; i < 4; i++)
            l_p[i] += __shfl_xor_sync(0xffffffffu, l_p[i], off);
    float inv[4];
#pragma unroll
    for (int i = 0; i < 4; i++) inv[i] = 1.0f / l_p[i];

    // output: for each dd, 4 consecutive rows -> one float4 store
#pragma unroll
    for (int dd = 0; dd < 4; dd++) {
        int d = cg + dd * 8;
        float2 a0 = unpack2(acc[0][dd]), a1 = unpack2(acc[1][dd]);
        float2 a2 = unpack2(acc[2][dd]), a3 = unpack2(acc[3][dd]);
        float4 o = make_float4((a0.x + a0.y) * inv[0], (a1.x + a1.y) * inv[1],
                               (a2.x + a2.y) * inv[2], (a3.x + a3.y) * inv[3]);
        *(float4*)(out + (size_t)(h * 32 + d) * N + n0 + rg * 4) = o;
    }
}

// ---------------- bilinear upsample (jax.image.resize), both scales ----------------
__global__ void upsample_all_kernel(const float* __restrict__ att, float* __restrict__ cat) {
    int b = blockIdx.x;
    const float* in; float* dst; int s, Hs, idx;
    if (b < 4096) { in = att;             dst = cat + (size_t)CC * NPIX;     s = 2; Hs = 32; idx = b * 256 + threadIdx.x; }
    else          { in = att + CC * 1024; dst = cat + (size_t)2 * CC * NPIX; s = 4; Hs = 16; idx = (b - 4096) * 256 + threadIdx.x; }
    int xo = idx & 63, yo = (idx >> 6) & 63, c = idx >> 12;
    float fs = 1.0f / s;
    float fy = (yo + 0.5f) * fs - 0.5f;
    float fx = (xo + 0.5f) * fs - 0.5f;
    float fy0 = floorf(fy), fx0 = floorf(fx);
    float wy = fy - fy0, wx = fx - fx0;
    int y0 = (int)fy0, x0 = (int)fx0;
    int y0c = max(y0, 0), y1c = min(y0 + 1, Hs - 1);
    int x0c = max(x0, 0), x1c = min(x0 + 1, Hs - 1);
    const float* ip = in + (size_t)c * Hs * Hs;
    float v00 = ip[y0c * Hs + x0c], v01 = ip[y0c * Hs + x1c];
    float v10 = ip[y1c * Hs + x0c], v11 = ip[y1c * Hs + x1c];
    float v0 = v00 + (v01 - v00) * wx;
    float v1 = v10 + (v11 - v10) * wx;
    dst[idx] = v0 + (v1 - v0) * wy;
}

// ---------------- host launch ----------------
extern "C" void kernel_launch(void* const* d_in, const int* in_sizes, int n_in,
                              void* d_out, int out_size) {
    const float* x     = (const float*)d_in[0];
    const float* dw_w  = (const float*)d_in[1];
    const float* dw_b  = (const float*)d_in[2];
    const float* pw_w  = (const float*)d_in[3];
    const float* pw_b  = (const float*)d_in[4];
    const float* pos_w = (const float*)d_in[5];
    const float* pos_b = (const float*)d_in[6];
    const float* fus_w = (const float*)d_in[7];
    const float* fus_b = (const float*)d_in[8];
    float* out = (float*)d_out;

    static int attr_done = 0;
    if (!attr_done) {
        cudaFuncSetAttribute(attn_all_kernel, cudaFuncAttributeMaxDynamicSharedMemorySize, 86528);
        attr_done = 1;
    }

    float *xs, *dw, *pos, *qkv, *att, *cat;
    cudaGetSymbolAddress((void**)&xs,  g_xs);
    cudaGetSymbolAddress((void**)&dw,  g_dw);
    cudaGetSymbolAddress((void**)&pos, g_pos);
    cudaGetSymbolAddress((void**)&qkv, g_qkv);
    cudaGetSymbolAddress((void**)&att, g_att);
    cudaGetSymbolAddress((void**)&cat, g_cat);

    float* xs2 = xs;
    float* xs4 = xs + CC * 1024;

    pool_all_kernel  <<<1280, 256>>>(x, xs2, xs4);
    dwconv_all_kernel<<<5376, 256>>>(x, xs2, xs4, dw_w, dw_b, pos_w, pos_b, dw, pos);
    qkv_gemm_kernel  <<<252, 256>>>(pw_w, dw, pw_b, pos, qkv);
    attn_all_kernel  <<<336, 256, 86528>>>(qkv, cat, att);
    upsample_all_kernel<<<8192, 256>>>(att, cat);
    fusion_gemm_kernel<<<64, 256>>>(fus_w, cat, fus_b, out);
}

// round 16
// speedup vs baseline: 1.4168x; 1.1517x over previous
#include <cuda_runtime.h>
#include <math.h>

#define CC 256
#define HH 64
#define NPIX (HH*HH)
typedef unsigned long long u64;

#define OFF2   (CC*NPIX)
#define OFF4   (CC*NPIX + CC*1024)
#define TOTPIX (NPIX + 1024 + 256)
#define QOFF2  (3*CC*NPIX)
#define QOFF4  (3*CC*NPIX + 3*CC*1024)

// ---------------- packed f32x2 helpers ----------------
__device__ __forceinline__ void ffma2(u64 &d, u64 a, u64 b) {
    asm("fma.rn.f32x2 %0, %1, %2, %0;" : "+l"(d) : "l"(a), "l"(b));
}
__device__ __forceinline__ void fadd2(u64 &d, u64 a) {
    asm("add.rn.f32x2 %0, %0, %1;" : "+l"(d) : "l"(a));   // packed float add (NOT integer +)
}
__device__ __forceinline__ u64 pack2(float lo, float hi) {
    u64 r; asm("mov.b64 %0, {%1, %2};" : "=l"(r) : "f"(lo), "f"(hi)); return r;
}
__device__ __forceinline__ float2 unpack2(u64 v) {
    float2 r; asm("mov.b64 {%0, %1}, %2;" : "=f"(r.x), "=f"(r.y) : "l"(v)); return r;
}

// ---------------- scratch ----------------
__device__ float g_xs [CC*(1024+256)];
__device__ float g_dw [CC*TOTPIX];
__device__ float g_pos[CC*TOTPIX];
__device__ float g_qkv[3*CC*TOTPIX];
__device__ float g_att[CC*(1024+256)];
__device__ float g_cat[3*CC*NPIX];

// ---------------- avg pool, both scales ----------------
__global__ void pool_all_kernel(const float* __restrict__ x,
                                float* __restrict__ xs2, float* __restrict__ xs4) {
    int b = blockIdx.x;
    int s, Hs, idx; float* out;
    if (b < 1024) { s = 2; Hs = 32; out = xs2; idx = b * 256 + threadIdx.x; }
    else          { s = 4; Hs = 16; out = xs4; idx = (b - 1024) * 256 + threadIdx.x; }
    int xo = idx % Hs, yo = (idx / Hs) % Hs, c = idx / (Hs * Hs);
    const float* xp = x + c * NPIX + (yo * s) * HH + xo * s;
    float sum = 0.f;
    for (int dy = 0; dy < s; dy++)
        for (int dx = 0; dx < s; dx++) sum += xp[dy * HH + dx];
    out[idx] = sum * (1.0f / (s * s));
}

// ---------------- fused depthwise 3x3 (dw + pos), all scales ----------------
__global__ void dwconv_all_kernel(const float* __restrict__ x,
                                  const float* __restrict__ xs2, const float* __restrict__ xs4,
                                  const float* __restrict__ dw_w, const float* __restrict__ dw_b,
                                  const float* __restrict__ pos_w, const float* __restrict__ pos_b,
                                  float* __restrict__ dwout, float* __restrict__ posout) {
    int b = blockIdx.x;
    int i, Hs, off, bl; const float* src;
    if (b < 4096)      { i = 0; Hs = 64; src = x;   off = 0;    bl = b; }
    else if (b < 5120) { i = 1; Hs = 32; src = xs2; off = OFF2; bl = b - 4096; }
    else               { i = 2; Hs = 16; src = xs4; off = OFF4; bl = b - 5120; }
    int idx = bl * 256 + threadIdx.x;
    int x0 = idx % Hs, y0 = (idx / Hs) % Hs, c = idx / (Hs * Hs);
    const float* xp = src + c * Hs * Hs;
    const float* wd = dw_w + i * CC * 9 + c * 9;
    const float* wp = pos_w + i * CC * 9 + c * 9;
    float a = dw_b[i * CC + c], p = pos_b[i * CC + c];
#pragma unroll
    for (int ky = 0; ky < 3; ky++) {
        int y = y0 + ky - 1;
        if ((unsigned)y >= (unsigned)Hs) continue;
#pragma unroll
        for (int kx = 0; kx < 3; kx++) {
            int xx = x0 + kx - 1;
            if ((unsigned)xx >= (unsigned)Hs) continue;
            float v = __ldg(xp + y * Hs + xx);
            a = fmaf(v, wd[ky * 3 + kx], a);
            p = fmaf(v, wp[ky * 3 + kx], p);
        }
    }
    dwout[off + idx]  = a;
    posout[off + idx] = p;
}

// ---------------- 128x128 GEMM tile, 8x8 micro, FFMA2 (pairs along m) ----------------
template <bool ADD_POS>
__device__ __forceinline__ void gemm_tile128(const float* __restrict__ W, const float* __restrict__ A,
                                             const float* __restrict__ bias, const float* __restrict__ pos,
                                             float* __restrict__ Cout, int Kd, int N, int m0, int n0) {
    __shared__ __align__(16) float Wt[16][132];   // [k][m]
    __shared__ __align__(16) float As[16][132];   // [k][n]
    int tid = threadIdx.x;
    int tm = tid >> 4, tn = tid & 15;
    int wm = tid >> 2, wk = (tid & 3) * 4;
    u64 acc[4][8] = {};                           // [m-pair][n]
    for (int k0 = 0; k0 < Kd; k0 += 16) {
#pragma unroll
        for (int r = 0; r < 2; r++) {
            int m = wm + r * 64;
            float4 wv = *(const float4*)(W + (size_t)(m0 + m) * Kd + k0 + wk);
            Wt[wk + 0][m] = wv.x; Wt[wk + 1][m] = wv.y;
            Wt[wk + 2][m] = wv.z; Wt[wk + 3][m] = wv.w;
        }
#pragma unroll
        for (int r = 0; r < 2; r++) {
            int idx = tid + r * 256;
            int k = idx >> 5, n4 = (idx & 31) * 4;
            *(float4*)(&As[k][n4]) = *(const float4*)(A + (size_t)(k0 + k) * N + n0 + n4);
        }
        __syncthreads();
#pragma unroll
        for (int k = 0; k < 16; k++) {
            ulonglong2 w01 = *(const ulonglong2*)(&Wt[k][tm * 8]);
            ulonglong2 w23 = *(const ulonglong2*)(&Wt[k][tm * 8 + 4]);
            float4 a0 = *(const float4*)(&As[k][tn * 8]);
            float4 a1 = *(const float4*)(&As[k][tn * 8 + 4]);
            u64 wp[4] = {w01.x, w01.y, w23.x, w23.y};
            u64 ad[8] = {pack2(a0.x, a0.x), pack2(a0.y, a0.y), pack2(a0.z, a0.z), pack2(a0.w, a0.w),
                         pack2(a1.x, a1.x), pack2(a1.y, a1.y), pack2(a1.z, a1.z), pack2(a1.w, a1.w)};
#pragma unroll
            for (int mp = 0; mp < 4; mp++)
#pragma unroll
                for (int j = 0; j < 8; j++)
                    ffma2(acc[mp][j], wp[mp], ad[j]);
        }
        __syncthreads();
    }
#pragma unroll
    for (int mp = 0; mp < 4; mp++) {
#pragma unroll
        for (int hh = 0; hh < 2; hh++) {
            int m = m0 + tm * 8 + mp * 2 + hh;
            float bv = bias[m];
            float v[8];
#pragma unroll
            for (int j = 0; j < 8; j++) {
                float2 p = unpack2(acc[mp][j]);
                v[j] = (hh ? p.y : p.x) + bv;
            }
            int n = n0 + tn * 8;
            if (ADD_POS) {
                if (m < 512) {
                    const float* pp = pos + (size_t)(m & 255) * N + n;
                    float4 p0 = *(const float4*)pp, p1 = *(const float4*)(pp + 4);
                    v[0] += p0.x; v[1] += p0.y; v[2] += p0.z; v[3] += p0.w;
                    v[4] += p1.x; v[5] += p1.y; v[6] += p1.z; v[7] += p1.w;
                }
            }
            float* cp = Cout + (size_t)m * N + n;
            *(float4*)cp       = make_float4(v[0], v[1], v[2], v[3]);
            *(float4*)(cp + 4) = make_float4(v[4], v[5], v[6], v[7]);
        }
    }
}

__global__ __launch_bounds__(256, 2)
void qkv_gemm_kernel(const float* __restrict__ pw_w, const float* __restrict__ dw,
                     const float* __restrict__ pw_b, const float* __restrict__ pos,
                     float* __restrict__ qkv) {
    int b = blockIdx.x;
    int i, N, bx, by, off, qoff;
    if (b < 192)      { i = 0; N = 4096; bx = b & 31;        by = b >> 5;        off = 0;    qoff = 0; }
    else if (b < 240) { i = 1; N = 1024; bx = (b - 192) & 7; by = (b - 192) >> 3; off = OFF2; qoff = QOFF2; }
    else              { i = 2; N = 256;  bx = (b - 240) & 1; by = (b - 240) >> 1; off = OFF4; qoff = QOFF4; }
    gemm_tile128<true>(pw_w + (size_t)i * 768 * 256, dw + off, pw_b + i * 768,
                       pos + off, qkv + qoff, 256, N, by * 128, bx * 128);
}

__global__ __launch_bounds__(256, 2)
void fusion_gemm_kernel(const float* __restrict__ fus_w, const float* __restrict__ cat,
                        const float* __restrict__ fus_b, float* __restrict__ out) {
    int b = blockIdx.x;
    gemm_tile128<false>(fus_w, cat, fus_b, nullptr, out, 3 * CC, NPIX,
                        (b >> 5) * 128, (b & 31) * 128);
}

// ---------------- flash attention: Q-tile 256, K-tile 64, 8x8 micro both phases ----------------
// smem: Qs[32][260] | Ks[2][32][68] | Vt[2][64][36] | S[256][68]  = 138752 B
#define SM_QS   0
#define SM_KS   (32*260)
#define SM_VT   (32*260 + 2*32*68)
#define SM_S    (32*260 + 2*32*68 + 2*64*36)

__global__ __launch_bounds__(256, 1)
void attn_all_kernel(const float* __restrict__ qkv_base, float* __restrict__ cat,
                     float* __restrict__ att) {
    extern __shared__ float sm[];
    float (*Qs)[260]    = (float(*)[260])(sm + SM_QS);
    float (*Ks)[32][68] = (float(*)[32][68])(sm + SM_KS);
    float (*Vt)[64][36] = (float(*)[64][36])(sm + SM_VT);
    float (*S)[68]      = (float(*)[68])(sm + SM_S);

    int b = blockIdx.x;
    const float* qkv; float* out; int N, h, n0;
    if (b < 128)      { qkv = qkv_base;         out = cat;             N = 4096; h = b >> 4;        n0 = (b & 15) * 256; }
    else if (b < 160) { qkv = qkv_base + QOFF2; out = att;             N = 1024; h = (b - 128) >> 2; n0 = ((b - 128) & 3) * 256; }
    else              { qkv = qkv_base + QOFF4; out = att + CC * 1024; N = 256;  h = b - 160;        n0 = 0; }

    int tid = threadIdx.x;
    const float scale = 0.17677669529663687f;    // 1/sqrt(32)
    const float* qb = qkv + (size_t)(h * 32) * N + n0;
    const float* kb = qkv + (size_t)(256 + h * 32) * N;
    const float* vb = qkv + (size_t)(512 + h * 32) * N;

    int rg = tid >> 3;          // 0..31: rows rg*8..+7 (warp w owns rows 32w..32w+31)
    int cg = tid & 7;           // QK: keys cg*8..+7
    int dg = tid & 3;           // PV: dims dg*8..+7
    int ms = (tid >> 2) & 1;    // PV: m-split (partner = tid ^ 4, same warp)

    // load Q tile 256x32, scaled
#pragma unroll
    for (int r = 0; r < 8; r++) {
        int idx = tid + r * 256;
        int d = idx >> 6, q4 = (idx & 63) * 4;
        float4 qv = *(const float4*)(qb + (size_t)d * N + q4);
        qv.x *= scale; qv.y *= scale; qv.z *= scale; qv.w *= scale;
        *(float4*)(&Qs[d][q4]) = qv;
    }

    float l_p[8] = {};
    u64 oacc[8][4] = {};        // [row][d-pair], lanes = (d, d+1)

    int ld_d = tid >> 4, ld_m = (tid & 15) * 4;
    float4 kr[2], vr[2];
#pragma unroll
    for (int r = 0; r < 2; r++) {
        int d = ld_d + r * 16;
        kr[r] = *(const float4*)(kb + (size_t)d * N + ld_m);
        vr[r] = *(const float4*)(vb + (size_t)d * N + ld_m);
    }
#pragma unroll
    for (int r = 0; r < 2; r++) {
        int d = ld_d + r * 16;
        *(float4*)(&Ks[0][d][ld_m]) = kr[r];
        Vt[0][ld_m + 0][d] = vr[r].x; Vt[0][ld_m + 1][d] = vr[r].y;
        Vt[0][ld_m + 2][d] = vr[r].z; Vt[0][ld_m + 3][d] = vr[r].w;
    }
    __syncthreads();

    int T = N >> 6;
    for (int t = 0; t < T; t++) {
        int cur = t & 1;
        if (t + 1 < T) {
            int m0 = (t + 1) * 64;
#pragma unroll
            for (int r = 0; r < 2; r++) {
                int d = ld_d + r * 16;
                kr[r] = *(const float4*)(kb + (size_t)d * N + m0 + ld_m);
                vr[r] = *(const float4*)(vb + (size_t)d * N + m0 + ld_m);
            }
        }

        // ---- S = Q^T K : 8 rows x 8 keys, acc pairs along keys, Q dup via ALU ----
        u64 sacc[8][4] = {};
#pragma unroll
        for (int d = 0; d < 32; d++) {
            float4 qa  = *(const float4*)(&Qs[d][rg * 8]);
            float4 qb2 = *(const float4*)(&Qs[d][rg * 8 + 4]);
            ulonglong2 k0 = *(const ulonglong2*)(&Ks[cur][d][cg * 8]);
            ulonglong2 k1 = *(const ulonglong2*)(&Ks[cur][d][cg * 8 + 4]);
            u64 qd[8] = {pack2(qa.x, qa.x),  pack2(qa.y, qa.y),
                         pack2(qa.z, qa.z),  pack2(qa.w, qa.w),
                         pack2(qb2.x, qb2.x), pack2(qb2.y, qb2.y),
                         pack2(qb2.z, qb2.z), pack2(qb2.w, qb2.w)};
#pragma unroll
            for (int i = 0; i < 8; i++) {
                ffma2(sacc[i][0], qd[i], k0.x); ffma2(sacc[i][1], qd[i], k0.y);
                ffma2(sacc[i][2], qd[i], k1.x); ffma2(sacc[i][3], qd[i], k1.y);
            }
        }

        // ---- exp (no max-sub: scores O(1), softmax shift-invariant), store S ----
#pragma unroll
        for (int i = 0; i < 8; i++) {
            float2 p0 = unpack2(sacc[i][0]), p1 = unpack2(sacc[i][1]);
            float2 p2 = unpack2(sacc[i][2]), p3 = unpack2(sacc[i][3]);
            float e0 = __expf(p0.x), e1 = __expf(p0.y), e2 = __expf(p1.x), e3 = __expf(p1.y);
            float e4 = __expf(p2.x), e5 = __expf(p2.y), e6 = __expf(p3.x), e7 = __expf(p3.y);
            l_p[i] += ((e0 + e1) + (e2 + e3)) + ((e4 + e5) + (e6 + e7));
            *(float4*)(&S[rg * 8 + i][cg * 8])     = make_float4(e0, e1, e2, e3);
            *(float4*)(&S[rg * 8 + i][cg * 8 + 4]) = make_float4(e4, e5, e6, e7);
        }
        __syncwarp();   // S rows 32w..32w+31 are warp-private

        // ---- O += P V^T : 8 rows x 8 dims, acc pairs along d, half the m4 groups ----
#define PV_STEP(COMP, M) { \
            ulonglong2 vv0 = *(const ulonglong2*)(&Vt[cur][(M)][dg * 8]); \
            ulonglong2 vv1 = *(const ulonglong2*)(&Vt[cur][(M)][dg * 8 + 4]); \
            _Pragma("unroll") \
            for (int i = 0; i < 8; i++) { \
                u64 sd = pack2(sr[i].COMP, sr[i].COMP); \
                ffma2(oacc[i][0], sd, vv0.x); ffma2(oacc[i][1], sd, vv0.y); \
                ffma2(oacc[i][2], sd, vv1.x); ffma2(oacc[i][3], sd, vv1.y); \
            } }
#pragma unroll
        for (int g = 0; g < 8; g++) {
            int m4 = g * 2 + ms;
            float4 sr[8];
#pragma unroll
            for (int i = 0; i < 8; i++)
                sr[i] = *(const float4*)(&S[rg * 8 + i][m4 * 4]);
            int mb = m4 * 4;
            PV_STEP(x, mb);
            PV_STEP(y, mb + 1);
            PV_STEP(z, mb + 2);
            PV_STEP(w, mb + 3);
        }
#undef PV_STEP

        if (t + 1 < T) {
#pragma unroll
            for (int r = 0; r < 2; r++) {
                int d = ld_d + r * 16;
                *(float4*)(&Ks[cur ^ 1][d][ld_m]) = kr[r];
                Vt[cur ^ 1][ld_m + 0][d] = vr[r].x; Vt[cur ^ 1][ld_m + 1][d] = vr[r].y;
                Vt[cur ^ 1][ld_m + 2][d] = vr[r].z; Vt[cur ^ 1][ld_m + 3][d] = vr[r].w;
            }
        }
        __syncthreads();
    }

    // merge m-split partner (tid ^ 4, same warp) — packed FLOAT add, not integer +=
#pragma unroll
    for (int i = 0; i < 8; i++)
#pragma unroll
        for (int j = 0; j < 4; j++) {
            u64 other = __shfl_xor_sync(0xffffffffu, oacc[i][j], 4);
            fadd2(oacc[i][j], other);
        }

    // reduce l over the 8 cg lanes (bits 0..2)
#pragma unroll
    for (int off = 1; off < 8; off <<= 1)
#pragma unroll
        for (int i = 0; i < 8; i++)
            l_p[i] += __shfl_xor_sync(0xffffffffu, l_p[i], off);
    float inv[8];
#pragma unroll
    for (int i = 0; i < 8; i++) inv[i] = 1.0f / l_p[i];

    // store: ms=0 writes d-pairs j=0,1 ; ms=1 writes j=2,3
#pragma unroll
    for (int jj = 0; jj < 2; jj++) {
        int j = ms * 2 + jj;
        int d0 = dg * 8 + 2 * j;
        float a[8], bb[8];
#pragma unroll
        for (int i = 0; i < 8; i++) {
            float2 p = unpack2(oacc[i][j]);
            a[i] = p.x * inv[i]; bb[i] = p.y * inv[i];
        }
        float* o0 = out + (size_t)(h * 32 + d0) * N + n0 + rg * 8;
        *(float4*)o0       = make_float4(a[0], a[1], a[2], a[3]);
        *(float4*)(o0 + 4) = make_float4(a[4], a[5], a[6], a[7]);
        float* o1 = out + (size_t)(h * 32 + d0 + 1) * N + n0 + rg * 8;
        *(float4*)o1       = make_float4(bb[0], bb[1], bb[2], bb[3]);
        *(float4*)(o1 + 4) = make_float4(bb[4], bb[5], bb[6], bb[7]);
    }
}

// ---------------- bilinear upsample (jax.image.resize), both scales ----------------
__global__ void upsample_all_kernel(const float* __restrict__ att, float* __restrict__ cat) {
    int b = blockIdx.x;
    const float* in; float* dst; int s, Hs, idx;
    if (b < 4096) { in = att;             dst = cat + (size_t)CC * NPIX;     s = 2; Hs = 32; idx = b * 256 + threadIdx.x; }
    else          { in = att + CC * 1024; dst = cat + (size_t)2 * CC * NPIX; s = 4; Hs = 16; idx = (b - 4096) * 256 + threadIdx.x; }
    int xo = idx & 63, yo = (idx >> 6) & 63, c = idx >> 12;
    float fs = 1.0f / s;
    float fy = (yo + 0.5f) * fs - 0.5f;
    float fx = (xo + 0.5f) * fs - 0.5f;
    float fy0 = floorf(fy), fx0 = floorf(fx);
    float wy = fy - fy0, wx = fx - fx0;
    int y0 = (int)fy0, x0 = (int)fx0;
    int y0c = max(y0, 0), y1c = min(y0 + 1, Hs - 1);
    int x0c = max(x0, 0), x1c = min(x0 + 1, Hs - 1);
    const float* ip = in + (size_t)c * Hs * Hs;
    float v00 = ip[y0c * Hs + x0c], v01 = ip[y0c * Hs + x1c];
    float v10 = ip[y1c * Hs + x0c], v11 = ip[y1c * Hs + x1c];
    float v0 = v00 + (v01 - v00) * wx;
    float v1 = v10 + (v11 - v10) * wx;
    dst[idx] = v0 + (v1 - v0) * wy;
}

// ---------------- host launch ----------------
extern "C" void kernel_launch(void* const* d_in, const int* in_sizes, int n_in,
                              void* d_out, int out_size) {
    const float* x     = (const float*)d_in[0];
    const float* dw_w  = (const float*)d_in[1];
    const float* dw_b  = (const float*)d_in[2];
    const float* pw_w  = (const float*)d_in[3];
    const float* pw_b  = (const float*)d_in[4];
    const float* pos_w = (const float*)d_in[5];
    const float* pos_b = (const float*)d_in[6];
    const float* fus_w = (const float*)d_in[7];
    const float* fus_b = (const float*)d_in[8];
    float* out = (float*)d_out;

    static int attr_done = 0;
    if (!attr_done) {
        cudaFuncSetAttribute(attn_all_kernel, cudaFuncAttributeMaxDynamicSharedMemorySize, 138752);
        attr_done = 1;
    }

    float *xs, *dw, *pos, *qkv, *att, *cat;
    cudaGetSymbolAddress((void**)&xs,  g_xs);
    cudaGetSymbolAddress((void**)&dw,  g_dw);
    cudaGetSymbolAddress((void**)&pos, g_pos);
    cudaGetSymbolAddress((void**)&qkv, g_qkv);
    cudaGetSymbolAddress((void**)&att, g_att);
    cudaGetSymbolAddress((void**)&cat, g_cat);

    float* xs2 = xs;
    float* xs4 = xs + CC * 1024;

    pool_all_kernel  <<<1280, 256>>>(x, xs2, xs4);
    dwconv_all_kernel<<<5376, 256>>>(x, xs2, xs4, dw_w, dw_b, pos_w, pos_b, dw, pos);
    qkv_gemm_kernel  <<<252, 256>>>(pw_w, dw, pw_b, pos, qkv);
    attn_all_kernel  <<<168, 256, 138752>>>(qkv, cat, att);
    upsample_all_kernel<<<8192, 256>>>(att, cat);
    fusion_gemm_kernel<<<64, 256>>>(fus_w, cat, fus_b, out);
}